// round 13
// baseline (speedup 1.0000x reference)
#include <cuda_runtime.h>
#include <cuda_bf16.h>

// ---- constants from the reference ----
#define ELE_FACTOR 332.0637f
#define EWALD_F    1.12837917f
#define EWALD_P    0.3275911f
#define EA0        0.254829592f
#define EA1       -0.284496736f
#define EA2        1.421413741f
#define EA3       -1.453152027f
#define EA4        1.061405429f
#define COUL_BETA  18.7f
#define COUL_R0    2.2f
#define G_EWALD    0.3f
#define R6_SHIFT   8303.765625f   // 4.5^6
#define INV_CUT6   1.0e-6f        // 1/10^6

#define MAX_ATOMS 200000
#define FULLMASK  0xffffffffu

// packed per-atom data (charge, sqrt(c6), r0, pad). 3.2 MB, L2-resident.
__device__ float4 g_atoms[MAX_ATOMS];

__global__ void pack_atoms_kernel(const float* __restrict__ q,
                                  const float* __restrict__ c6,
                                  const float* __restrict__ r0,
                                  int n) {
    int i = blockIdx.x * blockDim.x + threadIdx.x;
    if (i < n) {
        g_atoms[i] = make_float4(q[i], sqrtf(c6[i]), r0[i], 0.0f);
    }
}

// Per-edge physics from pre-reduced pair scalars.
// qq = qi*qj, c6ij = sqrt(c6i)*sqrt(c6j), r0s = r0i + r0j.
__device__ __forceinline__ void edge_compute(
    float dx, float dy, float dz, float qq, float c6ij, float r0s,
    float& ecoul, float& edisp, float& fc, float& fd)
{
    float r2     = dx * dx + dy * dy + dz * dz;
    float rinv   = rsqrtf(r2);
    float rij    = r2 * rinv;
    float inv_r2 = rinv * rinv;

    // ---------------- Coulomb ----------------
    float prefactor = ELE_FACTOR * qq * rinv;

    float x  = (COUL_BETA / COUL_R0) * (rij - COUL_R0);
    float ex = __expf(-fabsf(x));                     // in (0, 1]
    float inv1pex = __fdividef(1.0f, 1.0f + ex);
    float damp = (x >= 0.0f) ? inv1pex : (ex * inv1pex);   // stable sigmoid
    // softplus(x)/beta, stable
    float sp = (fmaxf(x, 0.0f) + __logf(1.0f + ex)) * (1.0f / COUL_BETA);
    float s  = rij * (1.0f / COUL_R0) * __fdividef(1.0f, 1.0f + sp);

    // Ewald short-range erfc correction
    float grij  = G_EWALD * rij;
    float expm2 = __expf(-grij * grij);
    float t     = __fdividef(1.0f, 1.0f + EWALD_P * grij);
    float erfc  = t * (EA0 + t * (EA1 + t * (EA2 + t * (EA3 + t * EA4)))) * expm2;

    ecoul = prefactor * (s + (erfc - 1.0f));
    float fcoul = prefactor * (damp * s * s + erfc + EWALD_F * grij * expm2 - 1.0f);
    fc = fcoul * inv_r2;

    // ---------------- Dispersion (D3-CSO) ----------------
    float r6     = r2 * r2 * r2 + R6_SHIFT;
    float inv_r6 = __fdividef(1.0f, r6);
    float e      = __expf(rij - 1.25f * r0s);          // rij - 2.5*r0ij
    float inv1pe = __fdividef(1.0f, 1.0f + e);
    float cso    = 0.85f + 0.82f * inv1pe;

    edisp = -c6ij * inv_r6 * cso + c6ij * INV_CUT6;
    float r5    = r2 * r2 * rij;
    float fdisp = -6.0f * c6ij * r5 * inv_r6 * inv_r6 * cso
                  - c6ij * inv_r6 * (0.82f * e * inv1pe * inv1pe);
    fd = fdisp * rinv;
}

// Persistent warp-tile kernel: each warp grid-strides over 32-edge tiles.
// Shuffle-transposed streaming I/O (wavefront floor) + software pipeline:
// next tile's row/col indices and dij float4s are prefetched one iteration
// ahead so their DRAM latency overlaps current-tile compute.
// Requires E % 4 == 0 for the float4 cf/df output regions.
__global__ void __launch_bounds__(256)
bamboo_edge_shfl_pipe(const int*    __restrict__ row,
                      const int*    __restrict__ col,
                      const float4* __restrict__ dij4,
                      float*        __restrict__ out,
                      int E, int ntiles, int nwarps_total) {
    int tid  = blockIdx.x * blockDim.x + threadIdx.x;
    int gw   = tid >> 5;
    int lane = tid & 31;

    int t = gw;
    if (t >= ntiles) return;

    // ---- prologue: load tile t's indices and dij ----
    int i0 = (t << 5) + lane;
    int ri = __ldcs(&row[i0]);
    int ci = __ldcs(&col[i0]);
    float4 D4 = make_float4(0.f, 0.f, 0.f, 0.f);
    if (lane < 24) D4 = __ldcs(&dij4[t * 24 + lane]);

    int q4 = (E >> 2);               // float4 count of one E-block
    float4* o4 = reinterpret_cast<float4*>(out);

    while (t < ntiles) {
        int tn = t + nwarps_total;
        int tc = (tn < ntiles) ? tn : t;     // clamp so prefetch is always legal

        // ---- gathers for current tile (indices already resident) ----
        float4 A = __ldcg(&g_atoms[ri]);
        float4 B = __ldcg(&g_atoms[ci]);

        // ---- prefetch next tile (overlaps with compute below) ----
        int in = (tc << 5) + lane;
        int ri_n = __ldcs(&row[in]);
        int ci_n = __ldcs(&col[in]);
        float4 D4n = make_float4(0.f, 0.f, 0.f, 0.f);
        if (lane < 24) D4n = __ldcs(&dij4[tc * 24 + lane]);

        // ---- distribute dij: lane needs pool floats 3*lane .. 3*lane+2 ----
        int f0 = 3 * lane;
        int a  = f0 >> 2;
        int o  = f0 & 3;
        float va0 = __shfl_sync(FULLMASK, D4.x, a);
        float va1 = __shfl_sync(FULLMASK, D4.y, a);
        float va2 = __shfl_sync(FULLMASK, D4.z, a);
        float va3 = __shfl_sync(FULLMASK, D4.w, a);
        float vb0 = __shfl_sync(FULLMASK, D4.x, a + 1);
        float vb1 = __shfl_sync(FULLMASK, D4.y, a + 1);

        bool o1 = (o & 1), o2 = (o & 2);
        float t01 = o1 ? va1 : va0, t23 = o1 ? va3 : va2;
        float dx  = o2 ? t23 : t01;
        float u12 = o1 ? va2 : va1;
        float u3x = o1 ? vb0 : va3;
        float dy  = o2 ? u3x : u12;
        float z01 = o1 ? va3 : va2;
        float z23 = o1 ? vb1 : vb0;
        float dz  = o2 ? z23 : z01;

        float qq = A.x * B.x, c6ij = A.y * B.y, r0s = A.z + B.z;
        float ec, ed, fc, fd;
        edge_compute(dx, dy, dz, qq, c6ij, r0s, ec, ed, fc, fd);

        int i = (t << 5) + lane;
        __stcs(&out[i], ec);
        __stcs(&out[(size_t)4 * E + i], ed);

        // ---- store transpose: lane j<24 writes cf/df float4 [4j,4j+4) ----
        int g0 = lane << 2;
        int e0 = g0 / 3;
        int p  = g0 - 3 * e0;
        float fca = __shfl_sync(FULLMASK, fc, e0);
        float fcb = __shfl_sync(FULLMASK, fc, e0 + 1);
        float fda = __shfl_sync(FULLMASK, fd, e0);
        float fdb = __shfl_sync(FULLMASK, fd, e0 + 1);

        float s1c = (p == 2) ? fcb : fca;
        float s2c = (p == 0) ? fca : fcb;
        float s1d = (p == 2) ? fdb : fda;
        float s2d = (p == 0) ? fda : fdb;

        if (lane < 24) {
            __stcs(&o4[(size_t)q4 + (size_t)t * 24 + lane],
                   make_float4(D4.x * fca, D4.y * s1c, D4.z * s2c, D4.w * fcb));
            __stcs(&o4[(size_t)q4 * 5 + (size_t)t * 24 + lane],
                   make_float4(D4.x * fda, D4.y * s1d, D4.z * s2d, D4.w * fdb));
        }

        // ---- rotate pipeline ----
        t  = tn;
        ri = ri_n;
        ci = ci_n;
        D4 = D4n;
    }
}

// scalar fallback/tail: handles edges [start, E)
__global__ void bamboo_edge_tail(const int*   __restrict__ row,
                                 const int*   __restrict__ col,
                                 const float* __restrict__ dij,
                                 float*       __restrict__ out,
                                 int E, int start) {
    int i = start + blockIdx.x * blockDim.x + threadIdx.x;
    if (i >= E) return;
    float dx = dij[3 * i + 0], dy = dij[3 * i + 1], dz = dij[3 * i + 2];
    float4 A = __ldcg(&g_atoms[row[i]]);
    float4 B = __ldcg(&g_atoms[col[i]]);
    float ecoul, edisp, fc, fd;
    edge_compute(dx, dy, dz, A.x * B.x, A.y * B.y, A.z + B.z,
                 ecoul, edisp, fc, fd);
    out[i] = ecoul;
    float* cf = out + (size_t)E + 3 * i;
    cf[0] = dx * fc; cf[1] = dy * fc; cf[2] = dz * fc;
    out[(size_t)4 * E + i] = edisp;
    float* df = out + (size_t)5 * E + 3 * i;
    df[0] = dx * fd; df[1] = dy * fd; df[2] = dz * fd;
}

extern "C" void kernel_launch(void* const* d_in, const int* in_sizes, int n_in,
                              void* d_out, int out_size) {
    const int*   row    = (const int*)d_in[0];
    const int*   col    = (const int*)d_in[1];
    const float* dij    = (const float*)d_in[2];
    const float* charge = (const float*)d_in[3];
    const float* c6     = (const float*)d_in[4];
    const float* r0     = (const float*)d_in[5];
    float* out = (float*)d_out;

    int E = in_sizes[0];
    int N = in_sizes[3];

    const int tpb = 256;
    pack_atoms_kernel<<<(N + tpb - 1) / tpb, tpb>>>(charge, c6, r0, N);

    if ((E & 3) == 0) {
        int ntiles = E >> 5;                 // full 32-edge tiles
        if (ntiles > 0) {
            int sms = 148;
            cudaDeviceGetAttribute(&sms, cudaDevAttrMultiProcessorCount, 0);
            int blocks = sms * 6;            // persistent-ish grid, 8 warps/block
            int nwarps_total = blocks * (tpb / 32);
            if (nwarps_total > ntiles) {     // shrink for tiny inputs
                blocks = (ntiles * 32 + tpb - 1) / tpb;
                nwarps_total = blocks * (tpb / 32);
            }
            bamboo_edge_shfl_pipe<<<blocks, tpb>>>(
                row, col, (const float4*)dij, out, E, ntiles, nwarps_total);
        }
        int done = ntiles << 5;
        if (done < E) {
            bamboo_edge_tail<<<1, tpb>>>(row, col, dij, out, E, done);
        }
    } else {
        // alignment fallback: plain scalar over everything
        bamboo_edge_tail<<<(E + tpb - 1) / tpb, tpb>>>(row, col, dij, out, E, 0);
    }
}

// round 15
// speedup vs baseline: 1.0078x; 1.0078x over previous
#include <cuda_runtime.h>
#include <cuda_bf16.h>

// ---- constants from the reference ----
#define ELE_FACTOR 332.0637f
#define EWALD_F    1.12837917f
#define EWALD_P    0.3275911f
#define EA0        0.254829592f
#define EA1       -0.284496736f
#define EA2        1.421413741f
#define EA3       -1.453152027f
#define EA4        1.061405429f
#define COUL_BETA  18.7f
#define COUL_R0    2.2f
#define G_EWALD    0.3f
#define R6_SHIFT   8303.765625f   // 4.5^6
#define INV_CUT6   1.0e-6f        // 1/10^6

#define MAX_ATOMS 200000
#define FULLMASK  0xffffffffu

// packed per-atom data (charge, sqrt(c6), r0, pad). 3.2 MB, L2-resident.
__device__ float4 g_atoms[MAX_ATOMS];

// vectorized pack: 4 atoms per thread
__global__ void pack_atoms_kernel4(const float4* __restrict__ q4,
                                   const float4* __restrict__ c64,
                                   const float4* __restrict__ r04,
                                   int nquads) {
    int i = blockIdx.x * blockDim.x + threadIdx.x;
    if (i < nquads) {
        float4 q = __ldcs(&q4[i]);
        float4 c = __ldcs(&c64[i]);
        float4 r = __ldcs(&r04[i]);
        g_atoms[4 * i + 0] = make_float4(q.x, sqrtf(c.x), r.x, 0.0f);
        g_atoms[4 * i + 1] = make_float4(q.y, sqrtf(c.y), r.y, 0.0f);
        g_atoms[4 * i + 2] = make_float4(q.z, sqrtf(c.z), r.z, 0.0f);
        g_atoms[4 * i + 3] = make_float4(q.w, sqrtf(c.w), r.w, 0.0f);
    }
}

// scalar pack for the tail / unaligned case
__global__ void pack_atoms_kernel(const float* __restrict__ q,
                                  const float* __restrict__ c6,
                                  const float* __restrict__ r0,
                                  int n, int start) {
    int i = start + blockIdx.x * blockDim.x + threadIdx.x;
    if (i < n) {
        g_atoms[i] = make_float4(q[i], sqrtf(c6[i]), r0[i], 0.0f);
    }
}

// Per-edge physics from pre-reduced pair scalars.
// qq = qi*qj, c6ij = sqrt(c6i)*sqrt(c6j), r0s = r0i + r0j.
__device__ __forceinline__ void edge_compute(
    float dx, float dy, float dz, float qq, float c6ij, float r0s,
    float& ecoul, float& edisp, float& fc, float& fd)
{
    float r2     = dx * dx + dy * dy + dz * dz;
    float rinv   = rsqrtf(r2);
    float rij    = r2 * rinv;
    float inv_r2 = rinv * rinv;

    // ---------------- Coulomb ----------------
    float prefactor = ELE_FACTOR * qq * rinv;

    float x  = (COUL_BETA / COUL_R0) * (rij - COUL_R0);
    float ex = __expf(-fabsf(x));                     // in (0, 1]
    float inv1pex = __fdividef(1.0f, 1.0f + ex);
    float damp = (x >= 0.0f) ? inv1pex : (ex * inv1pex);   // stable sigmoid
    // softplus(x)/beta, stable
    float sp = (fmaxf(x, 0.0f) + __logf(1.0f + ex)) * (1.0f / COUL_BETA);
    float s  = rij * (1.0f / COUL_R0) * __fdividef(1.0f, 1.0f + sp);

    // Ewald short-range erfc correction
    float grij  = G_EWALD * rij;
    float expm2 = __expf(-grij * grij);
    float t     = __fdividef(1.0f, 1.0f + EWALD_P * grij);
    float erfc  = t * (EA0 + t * (EA1 + t * (EA2 + t * (EA3 + t * EA4)))) * expm2;

    ecoul = prefactor * (s + (erfc - 1.0f));
    float fcoul = prefactor * (damp * s * s + erfc + EWALD_F * grij * expm2 - 1.0f);
    fc = fcoul * inv_r2;

    // ---------------- Dispersion (D3-CSO) ----------------
    float r6     = r2 * r2 * r2 + R6_SHIFT;
    float inv_r6 = __fdividef(1.0f, r6);
    float e      = __expf(rij - 1.25f * r0s);          // rij - 2.5*r0ij
    float inv1pe = __fdividef(1.0f, 1.0f + e);
    float cso    = 0.85f + 0.82f * inv1pe;

    edisp = -c6ij * inv_r6 * cso + c6ij * INV_CUT6;
    float r5    = r2 * r2 * rij;
    float fdisp = -6.0f * c6ij * r5 * inv_r6 * inv_r6 * cso
                  - c6ij * inv_r6 * (0.82f * e * inv1pe * inv1pe);
    fd = fdisp * rinv;
}

// 1 edge/thread scalar compute; dij loads and cf/df stores at the 128B-line
// wavefront floor via warp-cooperative float4 accesses + shuffles.
// 128-thread blocks: 30 regs x 128 thr -> 16 CTAs/SM = full warp slots,
// finer wave granularity than 256. Requires E % 4 == 0.
__global__ void __launch_bounds__(128)
bamboo_edge_shfl(const int*    __restrict__ row,
                 const int*    __restrict__ col,
                 const float4* __restrict__ dij4,
                 float*        __restrict__ out,
                 int E, int nwarps) {
    int tid  = blockIdx.x * blockDim.x + threadIdx.x;
    int w    = tid >> 5;
    int lane = tid & 31;
    if (w >= nwarps) return;

    int i = (w << 5) + lane;            // my edge (warp is always full)

    // gathers first (in flight during all the shuffle work)
    int ri = __ldcs(&row[i]);
    int ci = __ldcs(&col[i]);
    float4 A = __ldcg(&g_atoms[ri]);
    float4 B = __ldcg(&g_atoms[ci]);

    // cooperative dij load: lanes 0..23 load 24 consecutive float4s
    // (the warp's 96 dij floats = 32 edges). 384B = 3 lines = 3 wavefronts.
    float4 D4 = make_float4(0.f, 0.f, 0.f, 0.f);
    if (lane < 24) D4 = __ldcs(&dij4[w * 24 + lane]);

    // distribute: lane i needs pool floats 3i, 3i+1, 3i+2.
    // pool float f lives in lane f>>2, component f&3.
    int f0 = 3 * lane;
    int a  = f0 >> 2;
    int o  = f0 & 3;
    float va0 = __shfl_sync(FULLMASK, D4.x, a);
    float va1 = __shfl_sync(FULLMASK, D4.y, a);
    float va2 = __shfl_sync(FULLMASK, D4.z, a);
    float va3 = __shfl_sync(FULLMASK, D4.w, a);
    float vb0 = __shfl_sync(FULLMASK, D4.x, a + 1);
    float vb1 = __shfl_sync(FULLMASK, D4.y, a + 1);

    bool o1 = (o & 1), o2 = (o & 2);
    // dx = va[o]
    float t01 = o1 ? va1 : va0, t23 = o1 ? va3 : va2;
    float dx  = o2 ? t23 : t01;
    // dy = (o<3) ? va[o+1] : vb0
    float u12 = o1 ? va2 : va1;      // o=0 -> va1, o=1 -> va2
    float u3x = o1 ? vb0 : va3;      // o=2 -> va3, o=3 -> vb0
    float dy  = o2 ? u3x : u12;
    // dz = (o<2) ? va[o+2] : vb[o-2]
    float z01 = o1 ? va3 : va2;
    float z23 = o1 ? vb1 : vb0;
    float dz  = o2 ? z23 : z01;

    float qq = A.x * B.x, c6ij = A.y * B.y, r0s = A.z + B.z;
    float ec, ed, fc, fd;
    edge_compute(dx, dy, dz, qq, c6ij, r0s, ec, ed, fc, fd);

    // energies: coalesced scalar stores (already at the line floor)
    __stcs(&out[i], ec);
    __stcs(&out[(size_t)4 * E + i], ed);

    // store transpose: lane j<24 writes output float4 = pool floats [4j, 4j+4)
    // of cf (= dij * fc). Lane j already HOLDS those dij floats in D4; it only
    // needs fc/fd of the 1-2 source edges, fetched by shuffle.
    int g0 = lane << 2;
    int e0 = g0 / 3;                 // first source edge (lane within warp)
    int p  = g0 - 3 * e0;            // 0,1,2
    float fca = __shfl_sync(FULLMASK, fc, e0);
    float fcb = __shfl_sync(FULLMASK, fc, e0 + 1);
    float fda = __shfl_sync(FULLMASK, fd, e0);
    float fdb = __shfl_sync(FULLMASK, fd, e0 + 1);

    // component k source edge: e0 + {0, p==2, p>=1, 1}[k]
    float s1c = (p == 2) ? fcb : fca;
    float s2c = (p == 0) ? fca : fcb;
    float s1d = (p == 2) ? fdb : fda;
    float s2d = (p == 0) ? fda : fdb;

    if (lane < 24) {
        int q4 = (E >> 2);           // float4 count of one E-block (E%4==0)
        float4* o4 = reinterpret_cast<float4*>(out);
        __stcs(&o4[(size_t)q4 + (size_t)w * 24 + lane],
               make_float4(D4.x * fca, D4.y * s1c, D4.z * s2c, D4.w * fcb));
        __stcs(&o4[(size_t)q4 * 5 + (size_t)w * 24 + lane],
               make_float4(D4.x * fda, D4.y * s1d, D4.z * s2d, D4.w * fdb));
    }
}

// scalar fallback/tail: handles edges [start, E)
__global__ void bamboo_edge_tail(const int*   __restrict__ row,
                                 const int*   __restrict__ col,
                                 const float* __restrict__ dij,
                                 float*       __restrict__ out,
                                 int E, int start) {
    int i = start + blockIdx.x * blockDim.x + threadIdx.x;
    if (i >= E) return;
    float dx = dij[3 * i + 0], dy = dij[3 * i + 1], dz = dij[3 * i + 2];
    float4 A = __ldcg(&g_atoms[row[i]]);
    float4 B = __ldcg(&g_atoms[col[i]]);
    float ecoul, edisp, fc, fd;
    edge_compute(dx, dy, dz, A.x * B.x, A.y * B.y, A.z + B.z,
                 ecoul, edisp, fc, fd);
    out[i] = ecoul;
    float* cf = out + (size_t)E + 3 * i;
    cf[0] = dx * fc; cf[1] = dy * fc; cf[2] = dz * fc;
    out[(size_t)4 * E + i] = edisp;
    float* df = out + (size_t)5 * E + 3 * i;
    df[0] = dx * fd; df[1] = dy * fd; df[2] = dz * fd;
}

extern "C" void kernel_launch(void* const* d_in, const int* in_sizes, int n_in,
                              void* d_out, int out_size) {
    const int*   row    = (const int*)d_in[0];
    const int*   col    = (const int*)d_in[1];
    const float* dij    = (const float*)d_in[2];
    const float* charge = (const float*)d_in[3];
    const float* c6     = (const float*)d_in[4];
    const float* r0     = (const float*)d_in[5];
    float* out = (float*)d_out;

    int E = in_sizes[0];
    int N = in_sizes[3];

    // ---- pack atom table ----
    {
        const int tpb = 256;
        int nq = N >> 2;
        if (nq > 0) {
            pack_atoms_kernel4<<<(nq + tpb - 1) / tpb, tpb>>>(
                (const float4*)charge, (const float4*)c6, (const float4*)r0, nq);
        }
        int done = nq << 2;
        if (done < N) {
            pack_atoms_kernel<<<1, tpb>>>(charge, c6, r0, N, done);
        }
    }

    // ---- edge kernel ----
    const int tpb = 128;
    if ((E & 3) == 0) {
        int nwarps = E >> 5;                     // full warps of 32 edges
        if (nwarps > 0) {
            int threads = nwarps * 32;
            bamboo_edge_shfl<<<(threads + tpb - 1) / tpb, tpb>>>(
                row, col, (const float4*)dij, out, E, nwarps);
        }
        int done = nwarps << 5;
        if (done < E) {
            bamboo_edge_tail<<<1, tpb>>>(row, col, dij, out, E, done);
        }
    } else {
        // alignment fallback: plain scalar over everything
        bamboo_edge_tail<<<(E + tpb - 1) / tpb, tpb>>>(row, col, dij, out, E, 0);
    }
}